// round 10
// baseline (speedup 1.0000x reference)
#include <cuda_runtime.h>
#include <math.h>

#define BB 32
#define SS 4096
#define HH 1024
#define NCHUNK 64
#define CHUNK (SS / NCHUNK)            // 64 rows per CTA
#define NEG_BIG -1.0e9f

// ---- scratch (no allocations allowed) ----
__device__ float g_qp[4 * BB * HH];               // split-K(4) projected-query partials
__device__ float g_part_m[BB * NCHUNK];           // per-chunk running max
__device__ float g_part_l[BB * NCHUNK];           // per-chunk exp-sum
__device__ float g_part_acc[BB * NCHUNK * HH];    // per-chunk unnormalized context (8MB)

// ============================================================
// Kernel A: split-K(4) projection.
// grid (HH/4, 4, 4) = 4096 CTAs, 128 threads (4 warps).
// Dot length 256 -> short serial chains, high CTA count.
// ============================================================
__global__ void __launch_bounds__(128) proj_kernel(
    const float* __restrict__ query, const float* __restrict__ W)
{
    const int tid = threadIdx.x;
    const int w = tid >> 5, lane = tid & 31;
    const int o = blockIdx.x * 4 + w;
    const int b0 = blockIdx.y * 8;
    const int z = blockIdx.z;                      // k-quarter
    const int h0 = z * (HH / 4);                   // 0,256,512,768

    const float4* wrow = (const float4*)(W + (size_t)o * HH + h0);
    float4 wv[2];
    #pragma unroll
    for (int j = 0; j < 2; j++) wv[j] = wrow[j * 32 + lane];

    float p[8];
    #pragma unroll
    for (int bb = 0; bb < 8; bb++) {
        const float4* qq = (const float4*)(query + (size_t)(b0 + bb) * HH + h0);
        float4 q0 = __ldg(qq + lane), q1 = __ldg(qq + 32 + lane);
        p[bb] = wv[0].x * q0.x + wv[0].y * q0.y + wv[0].z * q0.z + wv[0].w * q0.w
              + wv[1].x * q1.x + wv[1].y * q1.y + wv[1].z * q1.z + wv[1].w * q1.w;
    }

    #pragma unroll
    for (int off = 16; off > 0; off >>= 1) {
        #pragma unroll
        for (int bb = 0; bb < 8; bb++)
            p[bb] += __shfl_xor_sync(0xffffffffu, p[bb], off);
    }
    if (lane == 0) {
        float* dst = g_qp + (size_t)z * BB * HH;
        #pragma unroll
        for (int bb = 0; bb < 8; bb++)
            dst[(size_t)(b0 + bb) * HH + o] = p[bb];
    }
}

// ============================================================
// Kernel B: fused scores + online softmax + context partial,
// MASK SKIP + IN-CTA COMPACTION.
// grid (NCHUNK, B) = 2048 CTAs, 256 threads (8 warps).
// Warp 0 ballots the 64-row chunk mask into a compacted index
// list (writes -1e9 scores for masked rows immediately); all
// warps consume unmasked rows round-robin -> per-warp load
// imbalance ~1.06 instead of ~1.45. Masked rows contribute
// exactly 0 to l/acc (fp32 underflow), identical to reference.
// ============================================================
__global__ void __launch_bounds__(256) flash_kernel(
    const float* __restrict__ keys,
    const int* __restrict__ mask,
    float* __restrict__ scores_out)
{
    const int chunk = blockIdx.x, b = blockIdx.y;
    const int tid = threadIdx.x, w = tid >> 5, lane = tid & 31;

    __shared__ float4 sq[HH / 4];          // 4KB projected query (sum of 4 partials)
    __shared__ float  s_m[8], s_l[8];
    __shared__ float4 s_acc[8][256];       // 32KB warp partial contexts
    __shared__ int    s_idx[CHUNK];
    __shared__ int    s_n;

    const int s0 = chunk * CHUNK;
    const int* mrow = mask + (size_t)b * SS;

    // q = sum of split-K(4) partials
    {
        const size_t base = (size_t)b * (HH / 4);
        const float4* q0 = (const float4*)(g_qp) + base;
        const float4* q1 = (const float4*)(g_qp + (size_t)BB * HH) + base;
        const float4* q2 = (const float4*)(g_qp + (size_t)2 * BB * HH) + base;
        const float4* q3 = (const float4*)(g_qp + (size_t)3 * BB * HH) + base;
        for (int i = tid; i < HH / 4; i += 256) {
            float4 a = q0[i], c2 = q1[i], d = q2[i], e2 = q3[i];
            sq[i] = make_float4(a.x + c2.x + d.x + e2.x, a.y + c2.y + d.y + e2.y,
                                a.z + c2.z + d.z + e2.z, a.w + c2.w + d.w + e2.w);
        }
    }

    // ---- compaction: warp 0 builds unmasked index list ----
    if (w == 0) {
        int base = 0;
        #pragma unroll
        for (int g = 0; g < CHUNK / 32; g++) {
            const int s = s0 + g * 32 + lane;
            const int mk = mrow[s];
            const unsigned bal = __ballot_sync(0xffffffffu, mk == 0);
            if (mk != 0) scores_out[(size_t)b * SS + s] = NEG_BIG;
            const int pos = base + __popc(bal & ((1u << lane) - 1u));
            if (mk == 0) s_idx[pos] = g * 32 + lane;
            base += __popc(bal);
        }
        if (lane == 0) s_n = base;
    }
    __syncthreads();

    const int n = s_n;

    if (n == 0) {
        // all 64 rows masked (p ~ 2^-64): match R9 semantics
        ((float4*)(g_part_acc + (size_t)(b * NCHUNK + chunk) * HH))[tid] =
            make_float4(0.f, 0.f, 0.f, 0.f);
        if (tid == 0) {
            g_part_m[b * NCHUNK + chunk] = NEG_BIG;
            g_part_l[b * NCHUNK + chunk] = (float)CHUNK;
        }
        return;
    }

    float4 acc[8];
    #pragma unroll
    for (int j = 0; j < 8; j++) acc[j] = make_float4(0.f, 0.f, 0.f, 0.f);
    float m = -INFINITY, l = 0.f;

    // ---- round-robin over compacted unmasked rows ----
    for (int i = w; i < n; i += 8) {
        const int s = s0 + s_idx[i];
        const float4* kp = (const float4*)(keys + ((size_t)b * SS + s) * HH);

        float4 kv[8];
        float p = 0.f;
        #pragma unroll
        for (int j = 0; j < 8; j++) {
            kv[j] = __ldcs(kp + j * 32 + lane);
            float4 qv = sq[j * 32 + lane];
            p += kv[j].x * qv.x + kv[j].y * qv.y +
                 kv[j].z * qv.z + kv[j].w * qv.w;
        }
        #pragma unroll
        for (int off = 16; off > 0; off >>= 1)
            p += __shfl_xor_sync(0xffffffffu, p, off);

        if (lane == 0) scores_out[(size_t)b * SS + s] = p;

        const float mn = fmaxf(m, p);
        const float c  = __expf(m - mn);      // exp(-inf)=0 on first row
        const float e  = __expf(p - mn);
        l = l * c + e;
        #pragma unroll
        for (int j = 0; j < 8; j++) {
            acc[j].x = acc[j].x * c + e * kv[j].x;
            acc[j].y = acc[j].y * c + e * kv[j].y;
            acc[j].z = acc[j].z * c + e * kv[j].z;
            acc[j].w = acc[j].w * c + e * kv[j].w;
        }
        m = mn;
    }

    // ---- combine 8 warps (warps with no rows: m=-inf, l=0 -> ew=0) ----
    if (lane == 0) { s_m[w] = m; s_l[w] = l; }
    #pragma unroll
    for (int j = 0; j < 8; j++) s_acc[w][j * 32 + lane] = acc[j];
    __syncthreads();

    float M = s_m[0];
    #pragma unroll
    for (int i = 1; i < 8; i++) M = fmaxf(M, s_m[i]);
    float ew[8], L = 0.f;
    #pragma unroll
    for (int i = 0; i < 8; i++) {
        ew[i] = (s_m[i] == -INFINITY) ? 0.f : __expf(s_m[i] - M);
        L += ew[i] * s_l[i];
    }

    float4 cacc = make_float4(0.f, 0.f, 0.f, 0.f);
    #pragma unroll
    for (int i = 0; i < 8; i++) {
        float4 v = s_acc[i][tid];
        cacc.x += ew[i] * v.x; cacc.y += ew[i] * v.y;
        cacc.z += ew[i] * v.z; cacc.w += ew[i] * v.w;
    }
    const int pidx = b * NCHUNK + chunk;
    ((float4*)(g_part_acc + (size_t)pidx * HH))[tid] = cacc;
    if (tid == 0) { g_part_m[pidx] = M; g_part_l[pidx] = L; }
}

// ============================================================
// Kernel C: combine chunk partials -> context; normalize raw
// scores -> weights. grid (B, 9).
// ============================================================
__global__ void __launch_bounds__(256) finalize_kernel(float* __restrict__ out)
{
    const int b = blockIdx.x, part = blockIdx.y, tid = threadIdx.x;

    float M = g_part_m[b * NCHUNK];
    #pragma unroll
    for (int c = 1; c < NCHUNK; c++) M = fmaxf(M, g_part_m[b * NCHUNK + c]);
    float L = 0.f;
    #pragma unroll
    for (int c = 0; c < NCHUNK; c++)
        L += __expf(g_part_m[b * NCHUNK + c] - M) * g_part_l[b * NCHUNK + c];
    const float invL = 1.f / L;

    if (part == 8) {
        float4 ctx = make_float4(0.f, 0.f, 0.f, 0.f);
        #pragma unroll 4
        for (int c = 0; c < NCHUNK; c++) {
            const float ew = __expf(g_part_m[b * NCHUNK + c] - M);
            float4 v = ((const float4*)(g_part_acc + (size_t)(b * NCHUNK + c) * HH))[tid];
            ctx.x += ew * v.x; ctx.y += ew * v.y;
            ctx.z += ew * v.z; ctx.w += ew * v.w;
        }
        ctx.x *= invL; ctx.y *= invL; ctx.z *= invL; ctx.w *= invL;
        ((float4*)(out + (size_t)b * HH))[tid] = ctx;
    } else {
        float* wout = out + (size_t)BB * HH + (size_t)b * SS + part * 512;
        #pragma unroll
        for (int s = tid; s < 512; s += 256)
            wout[s] = __expf(wout[s] - M) * invL;
    }
}

extern "C" void kernel_launch(void* const* d_in, const int* in_sizes, int n_in,
                              void* d_out, int out_size)
{
    const float* query = nullptr;
    const float* keys  = nullptr;
    const int*   mask  = nullptr;
    const float* W     = nullptr;
    for (int i = 0; i < n_in; i++) {
        switch (in_sizes[i]) {
            case BB * HH:        query = (const float*)d_in[i]; break;  // 32768
            case BB * SS * HH:   keys  = (const float*)d_in[i]; break;  // 134217728
            case BB * SS:        mask  = (const int*)d_in[i];   break;  // 131072
            case HH * HH:        W     = (const float*)d_in[i]; break;  // 1048576
            default: break;
        }
    }
    float* out = (float*)d_out;

    proj_kernel<<<dim3(HH / 4, 4, 4), 128>>>(query, W);
    flash_kernel<<<dim3(NCHUNK, BB), 256>>>(keys, mask, out + (size_t)BB * HH);
    finalize_kernel<<<dim3(BB, 9), 256>>>(out);
}

// round 11
// speedup vs baseline: 1.0525x; 1.0525x over previous
#include <cuda_runtime.h>
#include <math.h>

#define BB 32
#define SS 4096
#define HH 1024
#define NCHUNK 32
#define CHUNK (SS / NCHUNK)            // 128 rows per CTA
#define NEG_BIG -1.0e9f

// ---- scratch (no allocations allowed) ----
__device__ float g_qp[4 * BB * HH];               // split-K(4) projected-query partials
__device__ float g_part_m[BB * NCHUNK];           // per-chunk running max
__device__ float g_part_l[BB * NCHUNK];           // per-chunk exp-sum
__device__ float g_part_acc[BB * NCHUNK * HH];    // per-chunk unnormalized context (4MB)

// ============================================================
// Kernel A: split-K(4) projection. [UNCHANGED — 12.5us]
// grid (HH/4, 4, 4) = 4096 CTAs, 128 threads (4 warps).
// ============================================================
__global__ void __launch_bounds__(128) proj_kernel(
    const float* __restrict__ query, const float* __restrict__ W)
{
    const int tid = threadIdx.x;
    const int w = tid >> 5, lane = tid & 31;
    const int o = blockIdx.x * 4 + w;
    const int b0 = blockIdx.y * 8;
    const int z = blockIdx.z;                      // k-quarter
    const int h0 = z * (HH / 4);                   // 0,256,512,768

    const float4* wrow = (const float4*)(W + (size_t)o * HH + h0);
    float4 wv[2];
    #pragma unroll
    for (int j = 0; j < 2; j++) wv[j] = wrow[j * 32 + lane];

    float p[8];
    #pragma unroll
    for (int bb = 0; bb < 8; bb++) {
        const float4* qq = (const float4*)(query + (size_t)(b0 + bb) * HH + h0);
        float4 q0 = __ldg(qq + lane), q1 = __ldg(qq + 32 + lane);
        p[bb] = wv[0].x * q0.x + wv[0].y * q0.y + wv[0].z * q0.z + wv[0].w * q0.w
              + wv[1].x * q1.x + wv[1].y * q1.y + wv[1].z * q1.z + wv[1].w * q1.w;
    }

    #pragma unroll
    for (int off = 16; off > 0; off >>= 1) {
        #pragma unroll
        for (int bb = 0; bb < 8; bb++)
            p[bb] += __shfl_xor_sync(0xffffffffu, p[bb], off);
    }
    if (lane == 0) {
        float* dst = g_qp + (size_t)z * BB * HH;
        #pragma unroll
        for (int bb = 0; bb < 8; bb++)
            dst[(size_t)(b0 + bb) * HH + o] = p[bb];
    }
}

// ============================================================
// Kernel B: mask-skip flash with COMPACTION + NEXT-ROW PREFETCH.
// grid (NCHUNK, B) = 1024 CTAs, 256 threads (8 warps).
// Compacted unmasked index list (warp 0 ballot); warps consume
// round-robin i = w, w+8, ... Next row (i+8) is prefetched in
// two halves: pf[0..3] issued while the current row's softmax/
// acc tail runs, kv[4..7] issued right after kv is freed.
// Breaks the load->compute->load serialization per warp.
// ============================================================
__global__ void __launch_bounds__(256) flash_kernel(
    const float* __restrict__ keys,
    const int* __restrict__ mask,
    float* __restrict__ scores_out)
{
    const int chunk = blockIdx.x, b = blockIdx.y;
    const int tid = threadIdx.x, w = tid >> 5, lane = tid & 31;

    __shared__ float4 sq[HH / 4];          // 4KB projected query (sum of 4 partials)
    __shared__ float  s_m[8], s_l[8];
    __shared__ float4 s_acc[8][256];       // 32KB warp partial contexts
    __shared__ int    s_idx[CHUNK];
    __shared__ int    s_n;

    const int s0 = chunk * CHUNK;
    const int* mrow = mask + (size_t)b * SS;

    // q = sum of split-K(4) partials
    {
        const size_t base = (size_t)b * (HH / 4);
        const float4* q0 = (const float4*)(g_qp) + base;
        const float4* q1 = (const float4*)(g_qp + (size_t)BB * HH) + base;
        const float4* q2 = (const float4*)(g_qp + (size_t)2 * BB * HH) + base;
        const float4* q3 = (const float4*)(g_qp + (size_t)3 * BB * HH) + base;
        for (int i = tid; i < HH / 4; i += 256) {
            float4 a = q0[i], c2 = q1[i], d = q2[i], e2 = q3[i];
            sq[i] = make_float4(a.x + c2.x + d.x + e2.x, a.y + c2.y + d.y + e2.y,
                                a.z + c2.z + d.z + e2.z, a.w + c2.w + d.w + e2.w);
        }
    }

    // ---- compaction: warp 0 builds unmasked index list ----
    if (w == 0) {
        int base = 0;
        #pragma unroll
        for (int g = 0; g < CHUNK / 32; g++) {
            const int s = s0 + g * 32 + lane;
            const int mk = mrow[s];
            const unsigned bal = __ballot_sync(0xffffffffu, mk == 0);
            if (mk != 0) scores_out[(size_t)b * SS + s] = NEG_BIG;
            const int pos = base + __popc(bal & ((1u << lane) - 1u));
            if (mk == 0) s_idx[pos] = g * 32 + lane;
            base += __popc(bal);
        }
        if (lane == 0) s_n = base;
    }
    __syncthreads();

    const int n = s_n;

    if (n == 0) {
        ((float4*)(g_part_acc + (size_t)(b * NCHUNK + chunk) * HH))[tid] =
            make_float4(0.f, 0.f, 0.f, 0.f);
        if (tid == 0) {
            g_part_m[b * NCHUNK + chunk] = NEG_BIG;
            g_part_l[b * NCHUNK + chunk] = (float)CHUNK;
        }
        return;
    }

    float4 acc[8];
    #pragma unroll
    for (int j = 0; j < 8; j++) acc[j] = make_float4(0.f, 0.f, 0.f, 0.f);
    float m = -INFINITY, l = 0.f;

    const float* kb = keys + (size_t)b * SS * HH + (size_t)s0 * HH;

    float4 kv[8], pf[4];
    int i = w;
    if (i < n) {
        const float4* kp = (const float4*)(kb + (size_t)s_idx[i] * HH);
        #pragma unroll
        for (int j = 0; j < 8; j++) kv[j] = __ldcs(kp + j * 32 + lane);
    }

    while (i < n) {
        // dot on current row (2 independent partial chains)
        float pa = 0.f, pb = 0.f;
        #pragma unroll
        for (int j = 0; j < 8; j += 2) {
            float4 qe = sq[j * 32 + lane], qo = sq[(j + 1) * 32 + lane];
            pa += kv[j].x * qe.x + kv[j].y * qe.y + kv[j].z * qe.z + kv[j].w * qe.w;
            pb += kv[j+1].x * qo.x + kv[j+1].y * qo.y + kv[j+1].z * qo.z + kv[j+1].w * qo.w;
        }
        float p = pa + pb;

        // issue first half of NEXT row while the tail compute runs
        const int inext = i + 8;
        const float4* kpn = nullptr;
        if (inext < n) {
            kpn = (const float4*)(kb + (size_t)s_idx[inext] * HH);
            #pragma unroll
            for (int j = 0; j < 4; j++) pf[j] = __ldcs(kpn + j * 32 + lane);
        }

        #pragma unroll
        for (int off = 16; off > 0; off >>= 1)
            p += __shfl_xor_sync(0xffffffffu, p, off);

        const int s = s0 + s_idx[i];
        if (lane == 0) scores_out[(size_t)b * SS + s] = p;

        const float mn = fmaxf(m, p);
        const float c  = __expf(m - mn);      // exp(-inf)=0 on first row
        const float e  = __expf(p - mn);
        l = l * c + e;
        #pragma unroll
        for (int j = 0; j < 8; j++) {
            acc[j].x = acc[j].x * c + e * kv[j].x;
            acc[j].y = acc[j].y * c + e * kv[j].y;
            acc[j].z = acc[j].z * c + e * kv[j].z;
            acc[j].w = acc[j].w * c + e * kv[j].w;
        }
        m = mn;

        // kv is free: take prefetched half, issue second half
        if (inext < n) {
            #pragma unroll
            for (int j = 0; j < 4; j++) kv[j] = pf[j];
            #pragma unroll
            for (int j = 4; j < 8; j++) kv[j] = __ldcs(kpn + j * 32 + lane);
        }
        i = inext;
    }

    // ---- combine 8 warps (warps with no rows: m=-inf, l=0 -> ew=0) ----
    if (lane == 0) { s_m[w] = m; s_l[w] = l; }
    #pragma unroll
    for (int j = 0; j < 8; j++) s_acc[w][j * 32 + lane] = acc[j];
    __syncthreads();

    float M = s_m[0];
    #pragma unroll
    for (int i2 = 1; i2 < 8; i2++) M = fmaxf(M, s_m[i2]);
    float ew[8], L = 0.f;
    #pragma unroll
    for (int i2 = 0; i2 < 8; i2++) {
        ew[i2] = (s_m[i2] == -INFINITY) ? 0.f : __expf(s_m[i2] - M);
        L += ew[i2] * s_l[i2];
    }

    float4 cacc = make_float4(0.f, 0.f, 0.f, 0.f);
    #pragma unroll
    for (int i2 = 0; i2 < 8; i2++) {
        float4 v = s_acc[i2][tid];
        cacc.x += ew[i2] * v.x; cacc.y += ew[i2] * v.y;
        cacc.z += ew[i2] * v.z; cacc.w += ew[i2] * v.w;
    }
    const int pidx = b * NCHUNK + chunk;
    ((float4*)(g_part_acc + (size_t)pidx * HH))[tid] = cacc;
    if (tid == 0) { g_part_m[pidx] = M; g_part_l[pidx] = L; }
}

// ============================================================
// Kernel C: combine chunk partials -> context; normalize raw
// scores -> weights. grid (B, 9).
// ============================================================
__global__ void __launch_bounds__(256) finalize_kernel(float* __restrict__ out)
{
    const int b = blockIdx.x, part = blockIdx.y, tid = threadIdx.x;

    float M = g_part_m[b * NCHUNK];
    #pragma unroll
    for (int c = 1; c < NCHUNK; c++) M = fmaxf(M, g_part_m[b * NCHUNK + c]);
    float L = 0.f;
    #pragma unroll
    for (int c = 0; c < NCHUNK; c++)
        L += __expf(g_part_m[b * NCHUNK + c] - M) * g_part_l[b * NCHUNK + c];
    const float invL = 1.f / L;

    if (part == 8) {
        float4 ctx = make_float4(0.f, 0.f, 0.f, 0.f);
        #pragma unroll 4
        for (int c = 0; c < NCHUNK; c++) {
            const float ew = __expf(g_part_m[b * NCHUNK + c] - M);
            float4 v = ((const float4*)(g_part_acc + (size_t)(b * NCHUNK + c) * HH))[tid];
            ctx.x += ew * v.x; ctx.y += ew * v.y;
            ctx.z += ew * v.z; ctx.w += ew * v.w;
        }
        ctx.x *= invL; ctx.y *= invL; ctx.z *= invL; ctx.w *= invL;
        ((float4*)(out + (size_t)b * HH))[tid] = ctx;
    } else {
        float* wout = out + (size_t)BB * HH + (size_t)b * SS + part * 512;
        #pragma unroll
        for (int s = tid; s < 512; s += 256)
            wout[s] = __expf(wout[s] - M) * invL;
    }
}

extern "C" void kernel_launch(void* const* d_in, const int* in_sizes, int n_in,
                              void* d_out, int out_size)
{
    const float* query = nullptr;
    const float* keys  = nullptr;
    const int*   mask  = nullptr;
    const float* W     = nullptr;
    for (int i = 0; i < n_in; i++) {
        switch (in_sizes[i]) {
            case BB * HH:        query = (const float*)d_in[i]; break;  // 32768
            case BB * SS * HH:   keys  = (const float*)d_in[i]; break;  // 134217728
            case BB * SS:        mask  = (const int*)d_in[i];   break;  // 131072
            case HH * HH:        W     = (const float*)d_in[i]; break;  // 1048576
            default: break;
        }
    }
    float* out = (float*)d_out;

    proj_kernel<<<dim3(HH / 4, 4, 4), 128>>>(query, W);
    flash_kernel<<<dim3(NCHUNK, BB), 256>>>(keys, mask, out + (size_t)BB * HH);
    finalize_kernel<<<dim3(BB, 9), 256>>>(out);
}

// round 12
// speedup vs baseline: 1.0846x; 1.0306x over previous
#include <cuda_runtime.h>
#include <math.h>

#define BB 32
#define SS 4096
#define HH 1024
#define NCHUNK 32
#define CHUNK (SS / NCHUNK)            // 128 rows per tile
#define NTILES (NCHUNK * BB)           // 1024 work tiles
#define PERSIST 304                    // 2 CTAs/SM x 152 SMs
#define NEG_BIG -1.0e9f

// ---- scratch (no allocations allowed) ----
__device__ float g_qp[4 * BB * HH];               // split-K(4) projected-query partials
__device__ float g_part_m[BB * NCHUNK];           // per-chunk running max
__device__ float g_part_l[BB * NCHUNK];           // per-chunk exp-sum
__device__ float g_part_acc[BB * NCHUNK * HH];    // per-chunk unnormalized context (4MB)
__device__ unsigned int g_ctr;                    // persistent work counter

__global__ void reset_ctr_kernel() { g_ctr = 0u; }

// ============================================================
// Kernel A: split-K(4) projection with SMEM-STAGED Q.
// grid (HH/16, 4, 4) = 1024 CTAs, 128 threads (4 warps).
// q-quarter for 8 batches staged in smem ONCE per CTA (8KB):
// q L1 traffic 80MB -> 8MB (was the 51% L1 bottleneck).
// Warp computes 4 o-rows, all wv preloaded (no serialization).
// ============================================================
__global__ void __launch_bounds__(128) proj_kernel(
    const float* __restrict__ query, const float* __restrict__ W)
{
    __shared__ float4 sq2[8 * 64];     // 8 batches x 256 floats (k-quarter)
    const int tid = threadIdx.x;
    const int w = tid >> 5, lane = tid & 31;
    const int o0 = blockIdx.x * 16;
    const int b0 = blockIdx.y * 8;
    const int z = blockIdx.z;                      // k-quarter
    const int h0 = z * (HH / 4);                   // 0,256,512,768

    for (int i = tid; i < 8 * 64; i += 128) {
        const int bb = i >> 6, col = i & 63;
        sq2[i] = ((const float4*)(query + (size_t)(b0 + bb) * HH + h0))[col];
    }
    __syncthreads();

    // preload W for all 4 o-rows of this warp (8 independent loads)
    float4 wv[4][2];
    #pragma unroll
    for (int r = 0; r < 4; r++) {
        const float4* wrow = (const float4*)(W + (size_t)(o0 + w * 4 + r) * HH + h0);
        wv[r][0] = __ldg(wrow + lane);
        wv[r][1] = __ldg(wrow + 32 + lane);
    }

    #pragma unroll
    for (int r = 0; r < 4; r++) {
        float p[8];
        #pragma unroll
        for (int bb = 0; bb < 8; bb++) {
            const float4 q0 = sq2[bb * 64 + lane];
            const float4 q1 = sq2[bb * 64 + 32 + lane];
            p[bb] = wv[r][0].x * q0.x + wv[r][0].y * q0.y
                  + wv[r][0].z * q0.z + wv[r][0].w * q0.w
                  + wv[r][1].x * q1.x + wv[r][1].y * q1.y
                  + wv[r][1].z * q1.z + wv[r][1].w * q1.w;
        }
        #pragma unroll
        for (int off = 16; off > 0; off >>= 1) {
            #pragma unroll
            for (int bb = 0; bb < 8; bb++)
                p[bb] += __shfl_xor_sync(0xffffffffu, p[bb], off);
        }
        if (lane == 0) {
            float* dst = g_qp + (size_t)z * BB * HH;
            #pragma unroll
            for (int bb = 0; bb < 8; bb++)
                dst[(size_t)(b0 + bb) * HH + (o0 + w * 4 + r)] = p[bb];
        }
    }
}

// ============================================================
// Kernel B: PERSISTENT mask-skip flash (compaction + prefetch).
// grid 304 CTAs (2/SM), 256 threads. Tiles claimed dynamically
// via atomicAdd -> no wave quantization, per-tile n-variance
// absorbed by work stealing. Tile body identical to R11.
// ============================================================
__global__ void __launch_bounds__(256) flash_kernel(
    const float* __restrict__ keys,
    const int* __restrict__ mask,
    float* __restrict__ scores_out)
{
    const int tid = threadIdx.x, w = tid >> 5, lane = tid & 31;

    __shared__ float4 sq[HH / 4];          // 4KB projected query
    __shared__ float  s_m[8], s_l[8];
    __shared__ float4 s_acc[8][256];       // 32KB warp partial contexts
    __shared__ int    s_idx[CHUNK];
    __shared__ int    s_n;
    __shared__ int    s_tile;

    while (true) {
        if (tid == 0) s_tile = (int)atomicAdd(&g_ctr, 1u);
        __syncthreads();                   // also fences prev-tile smem reads
        const int t = s_tile;
        if (t >= NTILES) break;

        const int chunk = t & (NCHUNK - 1);
        const int b = t >> 5;
        const int s0 = chunk * CHUNK;
        const int* mrow = mask + (size_t)b * SS;

        // q = sum of split-K(4) partials
        {
            const size_t base = (size_t)b * (HH / 4);
            const float4* q0 = (const float4*)(g_qp) + base;
            const float4* q1 = (const float4*)(g_qp + (size_t)BB * HH) + base;
            const float4* q2 = (const float4*)(g_qp + (size_t)2 * BB * HH) + base;
            const float4* q3 = (const float4*)(g_qp + (size_t)3 * BB * HH) + base;
            for (int i = tid; i < HH / 4; i += 256) {
                float4 a = q0[i], c2 = q1[i], d = q2[i], e2 = q3[i];
                sq[i] = make_float4(a.x + c2.x + d.x + e2.x, a.y + c2.y + d.y + e2.y,
                                    a.z + c2.z + d.z + e2.z, a.w + c2.w + d.w + e2.w);
            }
        }

        // ---- compaction: warp 0 builds unmasked index list ----
        if (w == 0) {
            int base = 0;
            #pragma unroll
            for (int g = 0; g < CHUNK / 32; g++) {
                const int s = s0 + g * 32 + lane;
                const int mk = mrow[s];
                const unsigned bal = __ballot_sync(0xffffffffu, mk == 0);
                if (mk != 0) scores_out[(size_t)b * SS + s] = NEG_BIG;
                const int pos = base + __popc(bal & ((1u << lane) - 1u));
                if (mk == 0) s_idx[pos] = g * 32 + lane;
                base += __popc(bal);
            }
            if (lane == 0) s_n = base;
        }
        __syncthreads();

        const int n = s_n;
        const int pidx = b * NCHUNK + chunk;

        if (n == 0) {
            ((float4*)(g_part_acc + (size_t)pidx * HH))[tid] =
                make_float4(0.f, 0.f, 0.f, 0.f);
            if (tid == 0) {
                g_part_m[pidx] = NEG_BIG;
                g_part_l[pidx] = (float)CHUNK;
            }
            continue;
        }

        float4 acc[8];
        #pragma unroll
        for (int j = 0; j < 8; j++) acc[j] = make_float4(0.f, 0.f, 0.f, 0.f);
        float m = -INFINITY, l = 0.f;

        const float* kb = keys + (size_t)b * SS * HH + (size_t)s0 * HH;

        float4 kv[8], pf[4];
        int i = w;
        if (i < n) {
            const float4* kp = (const float4*)(kb + (size_t)s_idx[i] * HH);
            #pragma unroll
            for (int j = 0; j < 8; j++) kv[j] = __ldcs(kp + j * 32 + lane);
        }

        while (i < n) {
            float pa = 0.f, pb = 0.f;
            #pragma unroll
            for (int j = 0; j < 8; j += 2) {
                float4 qe = sq[j * 32 + lane], qo = sq[(j + 1) * 32 + lane];
                pa += kv[j].x * qe.x + kv[j].y * qe.y + kv[j].z * qe.z + kv[j].w * qe.w;
                pb += kv[j+1].x * qo.x + kv[j+1].y * qo.y + kv[j+1].z * qo.z + kv[j+1].w * qo.w;
            }
            float p = pa + pb;

            const int inext = i + 8;
            const float4* kpn = nullptr;
            if (inext < n) {
                kpn = (const float4*)(kb + (size_t)s_idx[inext] * HH);
                #pragma unroll
                for (int j = 0; j < 4; j++) pf[j] = __ldcs(kpn + j * 32 + lane);
            }

            #pragma unroll
            for (int off = 16; off > 0; off >>= 1)
                p += __shfl_xor_sync(0xffffffffu, p, off);

            const int s = s0 + s_idx[i];
            if (lane == 0) scores_out[(size_t)b * SS + s] = p;

            const float mn = fmaxf(m, p);
            const float c  = __expf(m - mn);
            const float e  = __expf(p - mn);
            l = l * c + e;
            #pragma unroll
            for (int j = 0; j < 8; j++) {
                acc[j].x = acc[j].x * c + e * kv[j].x;
                acc[j].y = acc[j].y * c + e * kv[j].y;
                acc[j].z = acc[j].z * c + e * kv[j].z;
                acc[j].w = acc[j].w * c + e * kv[j].w;
            }
            m = mn;

            if (inext < n) {
                #pragma unroll
                for (int j = 0; j < 4; j++) kv[j] = pf[j];
                #pragma unroll
                for (int j = 4; j < 8; j++) kv[j] = __ldcs(kpn + j * 32 + lane);
            }
            i = inext;
        }

        // ---- combine 8 warps ----
        if (lane == 0) { s_m[w] = m; s_l[w] = l; }
        #pragma unroll
        for (int j = 0; j < 8; j++) s_acc[w][j * 32 + lane] = acc[j];
        __syncthreads();

        float M = s_m[0];
        #pragma unroll
        for (int i2 = 1; i2 < 8; i2++) M = fmaxf(M, s_m[i2]);
        float ew[8], L = 0.f;
        #pragma unroll
        for (int i2 = 0; i2 < 8; i2++) {
            ew[i2] = (s_m[i2] == -INFINITY) ? 0.f : __expf(s_m[i2] - M);
            L += ew[i2] * s_l[i2];
        }

        float4 cacc = make_float4(0.f, 0.f, 0.f, 0.f);
        #pragma unroll
        for (int i2 = 0; i2 < 8; i2++) {
            float4 v = s_acc[i2][tid];
            cacc.x += ew[i2] * v.x; cacc.y += ew[i2] * v.y;
            cacc.z += ew[i2] * v.z; cacc.w += ew[i2] * v.w;
        }
        ((float4*)(g_part_acc + (size_t)pidx * HH))[tid] = cacc;
        if (tid == 0) { g_part_m[pidx] = M; g_part_l[pidx] = L; }
    }
}

// ============================================================
// Kernel C: combine chunk partials -> context; normalize raw
// scores -> weights. grid (B, 9).
// ============================================================
__global__ void __launch_bounds__(256) finalize_kernel(float* __restrict__ out)
{
    const int b = blockIdx.x, part = blockIdx.y, tid = threadIdx.x;

    float M = g_part_m[b * NCHUNK];
    #pragma unroll
    for (int c = 1; c < NCHUNK; c++) M = fmaxf(M, g_part_m[b * NCHUNK + c]);
    float L = 0.f;
    #pragma unroll
    for (int c = 0; c < NCHUNK; c++)
        L += __expf(g_part_m[b * NCHUNK + c] - M) * g_part_l[b * NCHUNK + c];
    const float invL = 1.f / L;

    if (part == 8) {
        float4 ctx = make_float4(0.f, 0.f, 0.f, 0.f);
        #pragma unroll 4
        for (int c = 0; c < NCHUNK; c++) {
            const float ew = __expf(g_part_m[b * NCHUNK + c] - M);
            float4 v = ((const float4*)(g_part_acc + (size_t)(b * NCHUNK + c) * HH))[tid];
            ctx.x += ew * v.x; ctx.y += ew * v.y;
            ctx.z += ew * v.z; ctx.w += ew * v.w;
        }
        ctx.x *= invL; ctx.y *= invL; ctx.z *= invL; ctx.w *= invL;
        ((float4*)(out + (size_t)b * HH))[tid] = ctx;
    } else {
        float* wout = out + (size_t)BB * HH + (size_t)b * SS + part * 512;
        #pragma unroll
        for (int s = tid; s < 512; s += 256)
            wout[s] = __expf(wout[s] - M) * invL;
    }
}

extern "C" void kernel_launch(void* const* d_in, const int* in_sizes, int n_in,
                              void* d_out, int out_size)
{
    const float* query = nullptr;
    const float* keys  = nullptr;
    const int*   mask  = nullptr;
    const float* W     = nullptr;
    for (int i = 0; i < n_in; i++) {
        switch (in_sizes[i]) {
            case BB * HH:        query = (const float*)d_in[i]; break;  // 32768
            case BB * SS * HH:   keys  = (const float*)d_in[i]; break;  // 134217728
            case BB * SS:        mask  = (const int*)d_in[i];   break;  // 131072
            case HH * HH:        W     = (const float*)d_in[i]; break;  // 1048576
            default: break;
        }
    }
    float* out = (float*)d_out;

    reset_ctr_kernel<<<1, 1>>>();
    proj_kernel<<<dim3(HH / 16, 4, 4), 128>>>(query, W);
    flash_kernel<<<PERSIST, 256>>>(keys, mask, out + (size_t)BB * HH);
    finalize_kernel<<<dim3(BB, 9), 256>>>(out);
}